// round 3
// baseline (speedup 1.0000x reference)
#include <cuda_runtime.h>
#include <cstdint>

// ---------------- problem constants ----------------
#define B_      32
#define TI_     4096
#define D_      512
#define ROWS_   (B_ * TI_)     // 131072 context rows
#define MT_     128            // rows per CTA
#define NC_     256            // d-columns per CTA (d-split = 2)
#define KT_     32             // K per tile
#define NKT_    (D_ / KT_)     // 16 k-tiles
#define NTILES_ (ROWS_ / MT_)  // 1024

// ---------------- scratch (device globals; no allocation allowed) ----------------
__device__ float g_qk[B_ * D_];       // folded q = output@Wq^T + bq + bk
__device__ float g_scores[ROWS_];     // pre-softmax scores (atomic partials)

// ---------------- smem layout for scores kernel (float offsets) ----------------
#define A_STRIDE 36
#define B_STRIDE 36
#define A_STAGE  (MT_ * A_STRIDE)        // 4608
#define B_STAGE  (NC_ * B_STRIDE)        // 9216
#define OFF_A    0
#define OFF_B    (2 * A_STAGE)           // 9216
#define OFF_QK   (OFF_B + 2 * B_STAGE)   // 27648
#define OFF_WV   (OFF_QK + NC_)
#define OFF_SP   (OFF_WV + NC_)          // 8 warps x 64 rows = 512
#define SMEM_FLOATS (OFF_SP + 512)
#define SMEM_BYTES  (SMEM_FLOATS * 4)    // 116736 B

__device__ __forceinline__ uint32_t smem_u32(const void* p) {
    uint32_t a;
    asm("{ .reg .u64 t; cvta.to.shared.u64 t, %1; cvt.u32.u64 %0, t; }" : "=r"(a) : "l"(p));
    return a;
}
__device__ __forceinline__ uint32_t f2tf32(float x) {
    uint32_t r;
    asm("cvt.rna.tf32.f32 %0, %1;" : "=r"(r) : "f"(x));
    return r;
}
__device__ __forceinline__ float tanh_fast(float x) {
    float t;
    asm("tanh.approx.f32 %0, %1;" : "=f"(t) : "f"(x));
    return t;
}

// ================= kernel 1: qk[b,d] = bq+bk + output[b]·Wq[d,:]; zero mix & scores ==========
__global__ void qk_kernel(const float* __restrict__ out_in, const float* __restrict__ Wq,
                          const float* __restrict__ bq, const float* __restrict__ bk,
                          float* __restrict__ mix) {
    int b = blockIdx.x, d = threadIdx.x;           // 512 threads, 32 blocks
    __shared__ float orow[D_];
    orow[d] = out_in[b * D_ + d];
    mix[b * D_ + d] = 0.0f;
    int gt = b * D_ + d;                            // 16384 global threads
    #pragma unroll
    for (int i = 0; i < ROWS_ / (B_ * D_); i++)     // 8 each
        g_scores[gt + i * B_ * D_] = 0.0f;
    __syncthreads();
    const float4* w = (const float4*)(Wq + (size_t)d * D_);
    float acc = bq[d] + bk[d];
    #pragma unroll 8
    for (int j = 0; j < D_ / 4; j++) {
        float4 t = w[j];
        acc = fmaf(t.x, orow[4*j], acc);
        acc = fmaf(t.y, orow[4*j+1], acc);
        acc = fmaf(t.z, orow[4*j+2], acc);
        acc = fmaf(t.w, orow[4*j+3], acc);
    }
    g_qk[b * D_ + d] = acc;
}

// ================= kernel 2: fused keys GEMM (tf32 mma.sync) + tanh + Wv reduce ==============
// grid (1024, 2): x = M tile (128 rows), y = d chunk (256 cols). 256 threads = 8 warps (2M x 4N).
__global__ void __launch_bounds__(256, 1)
scores_kernel(const float* __restrict__ ctx, const float* __restrict__ Wk,
              const float* __restrict__ Wv) {
    extern __shared__ float sm[];
    uint32_t sb = smem_u32(sm);
    int tid = threadIdx.x, lane = tid & 31, warp = tid >> 5;
    int wm = warp >> 2, wn = warp & 3;
    int tile = blockIdx.x, dc = blockIdx.y;
    int bidx = tile >> 5;                          // 32 tiles per batch
    size_t arow0 = (size_t)tile * MT_;
    const float* Ag = ctx + arow0 * D_;
    const float* Bg = Wk + (size_t)dc * NC_ * D_;

    for (int i = tid; i < NC_; i += 256) {
        sm[OFF_QK + i] = g_qk[bidx * D_ + dc * NC_ + i];
        sm[OFF_WV + i] = Wv[dc * NC_ + i];
    }

    float c[4][8][4];
    #pragma unroll
    for (int mi = 0; mi < 4; mi++)
        #pragma unroll
        for (int ni = 0; ni < 8; ni++)
            #pragma unroll
            for (int j = 0; j < 4; j++) c[mi][ni][j] = 0.0f;

    auto issue = [&](int kt, int s) {
        const float* a = Ag + kt * KT_;
        uint32_t abase = sb + (OFF_A + s * A_STAGE) * 4;
        #pragma unroll
        for (int i = 0; i < 4; i++) {              // A: 1024 16B chunks / 256 thr
            int idx = tid + 256 * i;
            int r = idx >> 3, sg = idx & 7;
            uint32_t sa = abase + (r * A_STRIDE + sg * 4) * 4;
            asm volatile("cp.async.cg.shared.global [%0], [%1], 16;"
                :: "r"(sa), "l"(a + (size_t)r * D_ + sg * 4));
        }
        const float* bsrc = Bg + kt * KT_;
        uint32_t bbase = sb + (OFF_B + s * B_STAGE) * 4;
        #pragma unroll
        for (int i = 0; i < 8; i++) {              // B: 2048 chunks / 256 thr
            int idx = tid + 256 * i;
            int r = idx >> 3, sg = idx & 7;
            uint32_t sa = bbase + (r * B_STRIDE + sg * 4) * 4;
            asm volatile("cp.async.cg.shared.global [%0], [%1], 16;"
                :: "r"(sa), "l"(bsrc + (size_t)r * D_ + sg * 4));
        }
        asm volatile("cp.async.commit_group;");
    };

    issue(0, 0);
    #pragma unroll 1
    for (int kt = 0; kt < NKT_; kt++) {
        if (kt + 1 < NKT_) {
            issue(kt + 1, (kt + 1) & 1);
            asm volatile("cp.async.wait_group 1;");
        } else {
            asm volatile("cp.async.wait_group 0;");
        }
        __syncthreads();
        const float* As_ = sm + OFF_A + (kt & 1) * A_STAGE;
        const float* Bs_ = sm + OFF_B + (kt & 1) * B_STAGE;
        #pragma unroll
        for (int ks = 0; ks < 4; ks++) {
            uint32_t af[4][4], bf[8][2];
            int c0 = ks * 8 + (lane & 3);
            int r0 = wm * 64 + (lane >> 2);
            #pragma unroll
            for (int mi = 0; mi < 4; mi++) {
                int r = r0 + mi * 16;
                af[mi][0] = f2tf32(As_[r * A_STRIDE + c0]);
                af[mi][1] = f2tf32(As_[(r + 8) * A_STRIDE + c0]);
                af[mi][2] = f2tf32(As_[r * A_STRIDE + c0 + 4]);
                af[mi][3] = f2tf32(As_[(r + 8) * A_STRIDE + c0 + 4]);
            }
            #pragma unroll
            for (int ni = 0; ni < 8; ni++) {
                int n = wn * 64 + ni * 8 + (lane >> 2);
                bf[ni][0] = f2tf32(Bs_[n * B_STRIDE + c0]);
                bf[ni][1] = f2tf32(Bs_[n * B_STRIDE + c0 + 4]);
            }
            #pragma unroll
            for (int mi = 0; mi < 4; mi++)
                #pragma unroll
                for (int ni = 0; ni < 8; ni++)
                    asm volatile(
                        "mma.sync.aligned.m16n8k8.row.col.f32.tf32.tf32.f32 "
                        "{%0,%1,%2,%3}, {%4,%5,%6,%7}, {%8,%9}, {%0,%1,%2,%3};"
                        : "+f"(c[mi][ni][0]), "+f"(c[mi][ni][1]),
                          "+f"(c[mi][ni][2]), "+f"(c[mi][ni][3])
                        : "r"(af[mi][0]), "r"(af[mi][1]), "r"(af[mi][2]), "r"(af[mi][3]),
                          "r"(bf[ni][0]), "r"(bf[ni][1]));
        }
        __syncthreads();
    }

    // ---- epilogue: score partial over this CTA's 256 d-cols ----
    const float* qs = sm + OFF_QK;
    const float* ws = sm + OFF_WV;
    float rs0[4] = {0, 0, 0, 0}, rs1[4] = {0, 0, 0, 0};
    #pragma unroll
    for (int mi = 0; mi < 4; mi++) {
        #pragma unroll
        for (int ni = 0; ni < 8; ni++) {
            int d0 = wn * 64 + ni * 8 + 2 * (lane & 3);
            float q0 = qs[d0], q1 = qs[d0 + 1];
            float w0 = ws[d0], w1 = ws[d0 + 1];
            rs0[mi] = fmaf(w0, tanh_fast(q0 + c[mi][ni][0]), rs0[mi]);
            rs0[mi] = fmaf(w1, tanh_fast(q1 + c[mi][ni][1]), rs0[mi]);
            rs1[mi] = fmaf(w0, tanh_fast(q0 + c[mi][ni][2]), rs1[mi]);
            rs1[mi] = fmaf(w1, tanh_fast(q1 + c[mi][ni][3]), rs1[mi]);
        }
        rs0[mi] += __shfl_xor_sync(0xffffffffu, rs0[mi], 1);
        rs0[mi] += __shfl_xor_sync(0xffffffffu, rs0[mi], 2);
        rs1[mi] += __shfl_xor_sync(0xffffffffu, rs1[mi], 1);
        rs1[mi] += __shfl_xor_sync(0xffffffffu, rs1[mi], 2);
    }
    float* sp = sm + OFF_SP;                       // [8 warps][64 rows]
    if ((lane & 3) == 0) {
        int g = lane >> 2;
        #pragma unroll
        for (int mi = 0; mi < 4; mi++) {
            sp[warp * 64 + mi * 16 + g]     = rs0[mi];
            sp[warp * 64 + mi * 16 + g + 8] = rs1[mi];
        }
    }
    __syncthreads();
    if (tid < MT_) {
        int wm2 = tid >> 6, rl = tid & 63;
        float s = sp[(wm2 * 4 + 0) * 64 + rl] + sp[(wm2 * 4 + 1) * 64 + rl]
                + sp[(wm2 * 4 + 2) * 64 + rl] + sp[(wm2 * 4 + 3) * 64 + rl];
        atomicAdd(&g_scores[arow0 + tid], s);
    }
}

// ================= kernel 3: softmax over Ti=4096 per batch (bv dropped: shift-invariant) =====
__device__ __forceinline__ float warpMax(float v) {
    #pragma unroll
    for (int o = 16; o; o >>= 1) v = fmaxf(v, __shfl_xor_sync(0xffffffffu, v, o));
    return v;
}
__device__ __forceinline__ float warpSum(float v) {
    #pragma unroll
    for (int o = 16; o; o >>= 1) v += __shfl_xor_sync(0xffffffffu, v, o);
    return v;
}

__global__ void softmax_kernel(float* __restrict__ attn) {
    int b = blockIdx.x, tid = threadIdx.x;         // 256 threads
    __shared__ float red[8];
    __shared__ float bc;
    const float* s = g_scores + b * TI_;
    float v[16];
    float mx = -3.0e38f;
    #pragma unroll
    for (int i = 0; i < 16; i++) { v[i] = s[tid + 256 * i]; mx = fmaxf(mx, v[i]); }
    mx = warpMax(mx);
    if ((tid & 31) == 0) red[tid >> 5] = mx;
    __syncthreads();
    if (tid < 32) { float m = (tid < 8) ? red[tid] : -3.0e38f; m = warpMax(m); if (tid == 0) bc = m; }
    __syncthreads();
    mx = bc;
    float sum = 0.0f;
    #pragma unroll
    for (int i = 0; i < 16; i++) { v[i] = __expf(v[i] - mx); sum += v[i]; }
    sum = warpSum(sum);
    if ((tid & 31) == 0) red[tid >> 5] = sum;
    __syncthreads();
    if (tid < 32) { float m = (tid < 8) ? red[tid] : 0.0f; m = warpSum(m); if (tid == 0) bc = m; }
    __syncthreads();
    float inv = 1.0f / bc;
    #pragma unroll
    for (int i = 0; i < 16; i++) attn[b * TI_ + tid + 256 * i] = v[i] * inv;
}

// ================= kernel 4: mix[b,d] = sum_t attn[b,t]*context[b,t,d] =================
#define MIX_SPLIT 32
#define MIX_TPB   (TI_ / MIX_SPLIT)   // 128 rows per block

__global__ void mix_kernel(const float* __restrict__ attn, const float* __restrict__ ctx,
                           float* __restrict__ mix) {
    int b = blockIdx.y, z = blockIdx.x, d = threadIdx.x;   // 512 threads
    __shared__ float sa[MIX_TPB];
    if (d < MIX_TPB) sa[d] = attn[b * TI_ + z * MIX_TPB + d];
    __syncthreads();
    const float* base = ctx + ((size_t)b * TI_ + (size_t)z * MIX_TPB) * D_ + d;
    float acc = 0.0f;
    #pragma unroll 8
    for (int t = 0; t < MIX_TPB; t++)
        acc = fmaf(sa[t], base[(size_t)t * D_], acc);
    atomicAdd(&mix[b * D_ + d], acc);
}

// ================= kernel 5: out = tanh([mix, output] @ Wo^T + bo) =================
__global__ void out_kernel(const float* __restrict__ mix, const float* __restrict__ out_in,
                           const float* __restrict__ Wo, const float* __restrict__ bo,
                           float* __restrict__ out) {
    int b = blockIdx.x, d = threadIdx.x;           // 512 threads
    __shared__ float comb[2 * D_];
    comb[d] = mix[b * D_ + d];
    comb[D_ + d] = out_in[b * D_ + d];
    __syncthreads();
    const float4* w = (const float4*)(Wo + (size_t)d * (2 * D_));
    float acc = bo[d];
    #pragma unroll 8
    for (int j = 0; j < (2 * D_) / 4; j++) {
        float4 t = w[j];
        acc = fmaf(t.x, comb[4*j], acc);
        acc = fmaf(t.y, comb[4*j+1], acc);
        acc = fmaf(t.z, comb[4*j+2], acc);
        acc = fmaf(t.w, comb[4*j+3], acc);
    }
    out[b * D_ + d] = tanhf(acc);
}

// ================= host launch =================
extern "C" void kernel_launch(void* const* d_in, const int* in_sizes, int n_in,
                              void* d_out, int out_size) {
    (void)in_sizes; (void)n_in; (void)out_size;
    const float* out_in  = (const float*)d_in[0];
    const float* context = (const float*)d_in[1];
    const float* Wq      = (const float*)d_in[2];
    const float* bq      = (const float*)d_in[3];
    const float* Wk      = (const float*)d_in[4];
    const float* bk      = (const float*)d_in[5];
    const float* Wv      = (const float*)d_in[6];
    const float* Wo      = (const float*)d_in[8];
    const float* bo      = (const float*)d_in[9];

    float* o_out  = (float*)d_out;                 // [32,1,512]
    float* o_attn = o_out + B_ * D_;               // [32,1,4096]
    float* o_mix  = o_attn + B_ * TI_;             // [32,1,512]

    static bool attr_done = false;
    if (!attr_done) {
        cudaFuncSetAttribute(scores_kernel, cudaFuncAttributeMaxDynamicSharedMemorySize, SMEM_BYTES);
        attr_done = true;
    }

    qk_kernel<<<B_, D_>>>(out_in, Wq, bq, bk, o_mix);
    scores_kernel<<<dim3(NTILES_, 2), 256, SMEM_BYTES>>>(context, Wk, Wv);
    softmax_kernel<<<B_, 256>>>(o_attn);
    mix_kernel<<<dim3(MIX_SPLIT, B_), D_>>>(o_attn, context, o_mix);
    out_kernel<<<B_, D_>>>(o_mix, out_in, Wo, bo, o_out);
}

// round 4
// speedup vs baseline: 1.0160x; 1.0160x over previous
#include <cuda_runtime.h>
#include <cstdint>

// ---------------- problem constants ----------------
#define B_      32
#define TI_     4096
#define D_      512
#define ROWS_   (B_ * TI_)     // 131072 context rows
#define MT_     128            // rows per CTA
#define NC_     256            // d-columns per CTA (d-split = 2)
#define KT_     32             // K per tile
#define NKT_    (D_ / KT_)     // 16 k-tiles
#define NTILES_ (ROWS_ / MT_)  // 1024

// ---------------- scratch (device globals; no allocation allowed) ----------------
__device__ float g_qk[B_ * D_];       // folded q = output@Wq^T + bq + bk
__device__ float g_scores[ROWS_];     // pre-softmax scores (atomic partials)

// ---------------- smem layout for scores kernel (float offsets) ----------------
#define A_STRIDE 36
#define B_STRIDE 36
#define A_STAGE  (MT_ * A_STRIDE)        // 4608
#define B_STAGE  (NC_ * B_STRIDE)        // 9216
#define OFF_A    0
#define OFF_B    (2 * A_STAGE)           // 9216
#define OFF_QK   (OFF_B + 2 * B_STAGE)   // 27648
#define OFF_WV   (OFF_QK + NC_)          // 27904
#define OFF_SP   (OFF_WV + NC_)          // 28160: 16 warps x 64 rows
#define SMEM_FLOATS (OFF_SP + 1024)      // 29184
#define SMEM_BYTES  (SMEM_FLOATS * 4)    // 116736 B -> 1 CTA/SM

__device__ __forceinline__ uint32_t smem_u32(const void* p) {
    uint32_t a;
    asm("{ .reg .u64 t; cvta.to.shared.u64 t, %1; cvt.u32.u64 %0, t; }" : "=r"(a) : "l"(p));
    return a;
}
__device__ __forceinline__ float tanh_fast(float x) {
    float t;
    asm("tanh.approx.f32 %0, %1;" : "=f"(t) : "f"(x));
    return t;
}

// ================= kernel 1: qk[b,d] = bq+bk + output[b]·Wq[d,:]; zero mix & scores ==========
__global__ void qk_kernel(const float* __restrict__ out_in, const float* __restrict__ Wq,
                          const float* __restrict__ bq, const float* __restrict__ bk,
                          float* __restrict__ mix) {
    int b = blockIdx.x, d = threadIdx.x;           // 512 threads, 32 blocks
    __shared__ float orow[D_];
    orow[d] = out_in[b * D_ + d];
    mix[b * D_ + d] = 0.0f;
    int gt = b * D_ + d;                            // 16384 global threads
    #pragma unroll
    for (int i = 0; i < ROWS_ / (B_ * D_); i++)     // 8 each
        g_scores[gt + i * B_ * D_] = 0.0f;
    __syncthreads();
    const float4* w = (const float4*)(Wq + (size_t)d * D_);
    float acc = bq[d] + bk[d];
    #pragma unroll 8
    for (int j = 0; j < D_ / 4; j++) {
        float4 t = w[j];
        acc = fmaf(t.x, orow[4*j], acc);
        acc = fmaf(t.y, orow[4*j+1], acc);
        acc = fmaf(t.z, orow[4*j+2], acc);
        acc = fmaf(t.w, orow[4*j+3], acc);
    }
    g_qk[b * D_ + d] = acc;
}

// ================= kernel 2: fused keys GEMM (tf32 mma.sync) + tanh + Wv reduce ==============
// grid (1024, 2): x = M tile (128 rows), y = d chunk (256 cols).
// 512 threads = 16 warps in a 2(M) x 8(N) grid; warp tile 64x32.
// No explicit f32->tf32 cvt: mma.tf32 HW reads the high 19 bits (RZ truncation).
__global__ void __launch_bounds__(512, 1)
scores_kernel(const float* __restrict__ ctx, const float* __restrict__ Wk,
              const float* __restrict__ Wv) {
    extern __shared__ float sm[];
    uint32_t sb = smem_u32(sm);
    int tid = threadIdx.x, lane = tid & 31, warp = tid >> 5;
    int wm = warp >> 3, wn = warp & 7;             // wm 0..1 (64 rows), wn 0..7 (32 cols)
    int tile = blockIdx.x, dc = blockIdx.y;
    int bidx = tile >> 5;                          // 32 tiles per batch
    size_t arow0 = (size_t)tile * MT_;
    const float* Ag = ctx + arow0 * D_;
    const float* Bg = Wk + (size_t)dc * NC_ * D_;

    if (tid < NC_) {
        sm[OFF_QK + tid] = g_qk[bidx * D_ + dc * NC_ + tid];
        sm[OFF_WV + tid] = Wv[dc * NC_ + tid];
    }

    float c[4][4][4];
    #pragma unroll
    for (int mi = 0; mi < 4; mi++)
        #pragma unroll
        for (int ni = 0; ni < 4; ni++)
            #pragma unroll
            for (int j = 0; j < 4; j++) c[mi][ni][j] = 0.0f;

    auto issue = [&](int kt, int s) {
        const float* a = Ag + kt * KT_;
        uint32_t abase = sb + (OFF_A + s * A_STAGE) * 4;
        #pragma unroll
        for (int i = 0; i < 2; i++) {              // A: 1024 16B granules / 512 thr
            int idx = tid + 512 * i;
            int r = idx >> 3, sg = idx & 7;
            uint32_t sa = abase + (r * A_STRIDE + sg * 4) * 4;
            asm volatile("cp.async.cg.shared.global [%0], [%1], 16;"
                :: "r"(sa), "l"(a + (size_t)r * D_ + sg * 4));
        }
        const float* bsrc = Bg + kt * KT_;
        uint32_t bbase = sb + (OFF_B + s * B_STAGE) * 4;
        #pragma unroll
        for (int i = 0; i < 4; i++) {              // B: 2048 granules / 512 thr
            int idx = tid + 512 * i;
            int r = idx >> 3, sg = idx & 7;
            uint32_t sa = bbase + (r * B_STRIDE + sg * 4) * 4;
            asm volatile("cp.async.cg.shared.global [%0], [%1], 16;"
                :: "r"(sa), "l"(bsrc + (size_t)r * D_ + sg * 4));
        }
        asm volatile("cp.async.commit_group;");
    };

    issue(0, 0);
    #pragma unroll 1
    for (int kt = 0; kt < NKT_; kt++) {
        if (kt + 1 < NKT_) {
            issue(kt + 1, (kt + 1) & 1);
            asm volatile("cp.async.wait_group 1;");
        } else {
            asm volatile("cp.async.wait_group 0;");
        }
        __syncthreads();
        const float* As_ = sm + OFF_A + (kt & 1) * A_STAGE;
        const float* Bs_ = sm + OFF_B + (kt & 1) * B_STAGE;
        #pragma unroll
        for (int ks = 0; ks < 4; ks++) {
            uint32_t af[4][4], bf[4][2];
            int c0 = ks * 8 + (lane & 3);
            int r0 = wm * 64 + (lane >> 2);
            #pragma unroll
            for (int mi = 0; mi < 4; mi++) {
                int r = r0 + mi * 16;
                af[mi][0] = __float_as_uint(As_[r * A_STRIDE + c0]);
                af[mi][1] = __float_as_uint(As_[(r + 8) * A_STRIDE + c0]);
                af[mi][2] = __float_as_uint(As_[r * A_STRIDE + c0 + 4]);
                af[mi][3] = __float_as_uint(As_[(r + 8) * A_STRIDE + c0 + 4]);
            }
            #pragma unroll
            for (int ni = 0; ni < 4; ni++) {
                int n = wn * 32 + ni * 8 + (lane >> 2);
                bf[ni][0] = __float_as_uint(Bs_[n * B_STRIDE + c0]);
                bf[ni][1] = __float_as_uint(Bs_[n * B_STRIDE + c0 + 4]);
            }
            #pragma unroll
            for (int mi = 0; mi < 4; mi++)
                #pragma unroll
                for (int ni = 0; ni < 4; ni++)
                    asm volatile(
                        "mma.sync.aligned.m16n8k8.row.col.f32.tf32.tf32.f32 "
                        "{%0,%1,%2,%3}, {%4,%5,%6,%7}, {%8,%9}, {%0,%1,%2,%3};"
                        : "+f"(c[mi][ni][0]), "+f"(c[mi][ni][1]),
                          "+f"(c[mi][ni][2]), "+f"(c[mi][ni][3])
                        : "r"(af[mi][0]), "r"(af[mi][1]), "r"(af[mi][2]), "r"(af[mi][3]),
                          "r"(bf[ni][0]), "r"(bf[ni][1]));
        }
        __syncthreads();
    }

    // ---- epilogue: score partial over this CTA's 256 d-cols ----
    const float* qs = sm + OFF_QK;
    const float* ws = sm + OFF_WV;
    float rs0[4] = {0, 0, 0, 0}, rs1[4] = {0, 0, 0, 0};
    #pragma unroll
    for (int mi = 0; mi < 4; mi++) {
        #pragma unroll
        for (int ni = 0; ni < 4; ni++) {
            int d0 = wn * 32 + ni * 8 + 2 * (lane & 3);
            float q0 = qs[d0], q1 = qs[d0 + 1];
            float w0 = ws[d0], w1 = ws[d0 + 1];
            rs0[mi] = fmaf(w0, tanh_fast(q0 + c[mi][ni][0]), rs0[mi]);
            rs0[mi] = fmaf(w1, tanh_fast(q1 + c[mi][ni][1]), rs0[mi]);
            rs1[mi] = fmaf(w0, tanh_fast(q0 + c[mi][ni][2]), rs1[mi]);
            rs1[mi] = fmaf(w1, tanh_fast(q1 + c[mi][ni][3]), rs1[mi]);
        }
        rs0[mi] += __shfl_xor_sync(0xffffffffu, rs0[mi], 1);
        rs0[mi] += __shfl_xor_sync(0xffffffffu, rs0[mi], 2);
        rs1[mi] += __shfl_xor_sync(0xffffffffu, rs1[mi], 1);
        rs1[mi] += __shfl_xor_sync(0xffffffffu, rs1[mi], 2);
    }
    float* sp = sm + OFF_SP;                       // [16 warps][64 rows]
    if ((lane & 3) == 0) {
        int g = lane >> 2;
        #pragma unroll
        for (int mi = 0; mi < 4; mi++) {
            sp[warp * 64 + mi * 16 + g]     = rs0[mi];
            sp[warp * 64 + mi * 16 + g + 8] = rs1[mi];
        }
    }
    __syncthreads();
    if (tid < MT_) {
        int wm2 = tid >> 6, rl = tid & 63;
        float s = 0.0f;
        #pragma unroll
        for (int w = 0; w < 8; w++)
            s += sp[(wm2 * 8 + w) * 64 + rl];
        atomicAdd(&g_scores[arow0 + tid], s);
    }
}

// ================= kernel 3: softmax over Ti=4096 per batch (bv dropped: shift-invariant) =====
__device__ __forceinline__ float warpMax(float v) {
    #pragma unroll
    for (int o = 16; o; o >>= 1) v = fmaxf(v, __shfl_xor_sync(0xffffffffu, v, o));
    return v;
}
__device__ __forceinline__ float warpSum(float v) {
    #pragma unroll
    for (int o = 16; o; o >>= 1) v += __shfl_xor_sync(0xffffffffu, v, o);
    return v;
}

__global__ void softmax_kernel(float* __restrict__ attn) {
    int b = blockIdx.x, tid = threadIdx.x;         // 256 threads
    __shared__ float red[8];
    __shared__ float bc;
    const float* s = g_scores + b * TI_;
    float v[16];
    float mx = -3.0e38f;
    #pragma unroll
    for (int i = 0; i < 16; i++) { v[i] = s[tid + 256 * i]; mx = fmaxf(mx, v[i]); }
    mx = warpMax(mx);
    if ((tid & 31) == 0) red[tid >> 5] = mx;
    __syncthreads();
    if (tid < 32) { float m = (tid < 8) ? red[tid] : -3.0e38f; m = warpMax(m); if (tid == 0) bc = m; }
    __syncthreads();
    mx = bc;
    float sum = 0.0f;
    #pragma unroll
    for (int i = 0; i < 16; i++) { v[i] = __expf(v[i] - mx); sum += v[i]; }
    sum = warpSum(sum);
    if ((tid & 31) == 0) red[tid >> 5] = sum;
    __syncthreads();
    if (tid < 32) { float m = (tid < 8) ? red[tid] : 0.0f; m = warpSum(m); if (tid == 0) bc = m; }
    __syncthreads();
    float inv = 1.0f / bc;
    #pragma unroll
    for (int i = 0; i < 16; i++) attn[b * TI_ + tid + 256 * i] = v[i] * inv;
}

// ================= kernel 4: mix[b,d] = sum_t attn[b,t]*context[b,t,d] =================
#define MIX_SPLIT 32
#define MIX_TPB   (TI_ / MIX_SPLIT)   // 128 rows per block

__global__ void mix_kernel(const float* __restrict__ attn, const float* __restrict__ ctx,
                           float* __restrict__ mix) {
    int b = blockIdx.y, z = blockIdx.x, d = threadIdx.x;   // 512 threads
    __shared__ float sa[MIX_TPB];
    if (d < MIX_TPB) sa[d] = attn[b * TI_ + z * MIX_TPB + d];
    __syncthreads();
    const float* base = ctx + ((size_t)b * TI_ + (size_t)z * MIX_TPB) * D_ + d;
    float acc = 0.0f;
    #pragma unroll 8
    for (int t = 0; t < MIX_TPB; t++)
        acc = fmaf(sa[t], base[(size_t)t * D_], acc);
    atomicAdd(&mix[b * D_ + d], acc);
}

// ================= kernel 5: out = tanh([mix, output] @ Wo^T + bo) =================
__global__ void out_kernel(const float* __restrict__ mix, const float* __restrict__ out_in,
                           const float* __restrict__ Wo, const float* __restrict__ bo,
                           float* __restrict__ out) {
    int b = blockIdx.x, d = threadIdx.x;           // 512 threads
    __shared__ float comb[2 * D_];
    comb[d] = mix[b * D_ + d];
    comb[D_ + d] = out_in[b * D_ + d];
    __syncthreads();
    const float4* w = (const float4*)(Wo + (size_t)d * (2 * D_));
    float acc = bo[d];
    #pragma unroll 8
    for (int j = 0; j < (2 * D_) / 4; j++) {
        float4 t = w[j];
        acc = fmaf(t.x, comb[4*j], acc);
        acc = fmaf(t.y, comb[4*j+1], acc);
        acc = fmaf(t.z, comb[4*j+2], acc);
        acc = fmaf(t.w, comb[4*j+3], acc);
    }
    out[b * D_ + d] = tanhf(acc);
}

// ================= host launch =================
extern "C" void kernel_launch(void* const* d_in, const int* in_sizes, int n_in,
                              void* d_out, int out_size) {
    (void)in_sizes; (void)n_in; (void)out_size;
    const float* out_in  = (const float*)d_in[0];
    const float* context = (const float*)d_in[1];
    const float* Wq      = (const float*)d_in[2];
    const float* bq      = (const float*)d_in[3];
    const float* Wk      = (const float*)d_in[4];
    const float* bk      = (const float*)d_in[5];
    const float* Wv      = (const float*)d_in[6];
    const float* Wo      = (const float*)d_in[8];
    const float* bo      = (const float*)d_in[9];

    float* o_out  = (float*)d_out;                 // [32,1,512]
    float* o_attn = o_out + B_ * D_;               // [32,1,4096]
    float* o_mix  = o_attn + B_ * TI_;             // [32,1,512]

    static bool attr_done = false;
    if (!attr_done) {
        cudaFuncSetAttribute(scores_kernel, cudaFuncAttributeMaxDynamicSharedMemorySize, SMEM_BYTES);
        attr_done = true;
    }

    qk_kernel<<<B_, D_>>>(out_in, Wq, bq, bk, o_mix);
    scores_kernel<<<dim3(NTILES_, 2), 512, SMEM_BYTES>>>(context, Wk, Wv);
    softmax_kernel<<<B_, 256>>>(o_attn);
    mix_kernel<<<dim3(MIX_SPLIT, B_), D_>>>(o_attn, context, o_mix);
    out_kernel<<<B_, D_>>>(o_mix, out_in, Wo, bo, o_out);
}

// round 5
// speedup vs baseline: 1.3806x; 1.3589x over previous
#include <cuda_runtime.h>
#include <cuda_fp16.h>
#include <cstdint>

// ---------------- problem constants ----------------
#define B_      32
#define TI_     4096
#define D_      512
#define ROWS_   (B_ * TI_)     // 131072 context rows
#define MT_     128            // rows per CTA
#define NC_     256            // d-columns per CTA (d-split = 2)
#define KT_     64             // K per tile (halves)
#define NKT_    (D_ / KT_)     // 8 k-tiles
#define NTILES_ (ROWS_ / MT_)  // 1024

// ---------------- scratch (device globals; no allocation allowed) ----------------
__device__ float  g_qk[B_ * D_];            // folded q = output@Wq^T + bq + bk
__device__ float  g_scores[ROWS_];          // pre-softmax scores (atomic partials)
__device__ __half2 g_ctxh[ROWS_ * D_ / 2];  // fp16 context (134 MB)
__device__ __half2 g_wkh[D_ * D_ / 2];      // fp16 Wk

// ---------------- smem layout (bytes) ----------------
#define AS_BYTES 144                       // 64 halves + 8 pad (ldmatrix conflict-free)
#define A_STAGE  (MT_ * AS_BYTES)          // 18432
#define B_STAGE  (NC_ * AS_BYTES)          // 36864
#define OFF_A    0                         // 3 A stages
#define OFF_B    (3 * A_STAGE)             // 55296, 3 B stages
#define OFF_QK   (OFF_B + 3 * B_STAGE)     // 165888
#define OFF_WV   (OFF_QK + 1024)           // 166912
#define OFF_SP   (OFF_WV + 1024)           // 167936 (16 warps x 64 rows x 4B)
#define SMEM_BYTES (OFF_SP + 4096)         // 172032

__device__ __forceinline__ uint32_t smem_u32(const void* p) {
    uint32_t a;
    asm("{ .reg .u64 t; cvta.to.shared.u64 t, %1; cvt.u32.u64 %0, t; }" : "=r"(a) : "l"(p));
    return a;
}
__device__ __forceinline__ float tanh_fast(float x) {
    float t;
    asm("tanh.approx.f32 %0, %1;" : "=f"(t) : "f"(x));
    return t;
}

// ================= kernel 0: fp32 -> fp16 conversion of context and Wk =================
__global__ void cvt_kernel(const float* __restrict__ ctx, const float* __restrict__ wk) {
    long idx = (long)blockIdx.x * 256 + threadIdx.x;     // one float4 per thread
    const long NCTX4 = (long)ROWS_ * D_ / 4;             // 16777216
    if (idx < NCTX4) {
        float4 v = ((const float4*)ctx)[idx];
        g_ctxh[2 * idx]     = __float22half2_rn(make_float2(v.x, v.y));
        g_ctxh[2 * idx + 1] = __float22half2_rn(make_float2(v.z, v.w));
    } else {
        long j = idx - NCTX4;                            // Wk: 65536 float4s
        float4 v = ((const float4*)wk)[j];
        g_wkh[2 * j]     = __float22half2_rn(make_float2(v.x, v.y));
        g_wkh[2 * j + 1] = __float22half2_rn(make_float2(v.z, v.w));
    }
}

__global__ void dummy_kernel() {}

// ================= kernel 1: qk[b,d] = bq+bk + output[b]·Wq[d,:]; zero mix & scores ==========
__global__ void qk_kernel(const float* __restrict__ out_in, const float* __restrict__ Wq,
                          const float* __restrict__ bq, const float* __restrict__ bk,
                          float* __restrict__ mix) {
    int b = blockIdx.x, d = threadIdx.x;           // 512 threads, 32 blocks
    __shared__ float orow[D_];
    orow[d] = out_in[b * D_ + d];
    mix[b * D_ + d] = 0.0f;
    int gt = b * D_ + d;
    #pragma unroll
    for (int i = 0; i < ROWS_ / (B_ * D_); i++)
        g_scores[gt + i * B_ * D_] = 0.0f;
    __syncthreads();
    const float4* w = (const float4*)(Wq + (size_t)d * D_);
    float acc = bq[d] + bk[d];
    #pragma unroll 8
    for (int j = 0; j < D_ / 4; j++) {
        float4 t = w[j];
        acc = fmaf(t.x, orow[4*j], acc);
        acc = fmaf(t.y, orow[4*j+1], acc);
        acc = fmaf(t.z, orow[4*j+2], acc);
        acc = fmaf(t.w, orow[4*j+3], acc);
    }
    g_qk[b * D_ + d] = acc;
}

// ================= kernel 2: fused keys GEMM (fp16 m16n8k16) + tanh + Wv reduce ==============
// grid (1024, 2). 512 threads = 16 warps, 2(M)x8(N), warp tile 64x32. 3-stage cp.async.
__global__ void __launch_bounds__(512, 1)
scores_kernel(const float* __restrict__ Wv) {
    extern __shared__ char sm[];
    uint32_t sb = smem_u32(sm);
    int tid = threadIdx.x, lane = tid & 31, warp = tid >> 5;
    int wm = warp >> 3, wn = warp & 7;
    int tile = blockIdx.x, dc = blockIdx.y;
    int bidx = tile >> 5;
    size_t arow0 = (size_t)tile * MT_;
    const __half* Ag = (const __half*)g_ctxh + arow0 * D_;
    const __half* Bg = (const __half*)g_wkh + (size_t)dc * NC_ * D_;

    float* sqk = (float*)(sm + OFF_QK);
    float* swv = (float*)(sm + OFF_WV);
    if (tid < NC_) {
        sqk[tid] = g_qk[bidx * D_ + dc * NC_ + tid];
        swv[tid] = Wv[dc * NC_ + tid];
    }

    float c[4][4][4];
    #pragma unroll
    for (int mi = 0; mi < 4; mi++)
        #pragma unroll
        for (int ni = 0; ni < 4; ni++)
            #pragma unroll
            for (int j = 0; j < 4; j++) c[mi][ni][j] = 0.0f;

    // per-lane ldmatrix base offsets (bytes within a stage)
    uint32_t a_off = (uint32_t)((wm * 64 + (lane & 15)) * AS_BYTES + (lane >> 4) * 16);
    uint32_t b_off = (uint32_t)((wn * 32 + ((lane >> 4) & 1) * 8 + (lane & 7)) * AS_BYTES
                                + ((lane >> 3) & 1) * 16);

    auto issue = [&](int kt) {
        int s = kt % 3;
        const __half* a = Ag + kt * KT_;
        uint32_t abase = sb + OFF_A + s * A_STAGE;
        #pragma unroll
        for (int i = 0; i < 2; i++) {              // A: 1024 16B granules / 512 thr
            int idx = tid + 512 * i;
            int r = idx >> 3, cg = idx & 7;
            asm volatile("cp.async.cg.shared.global [%0], [%1], 16;"
                :: "r"(abase + r * AS_BYTES + cg * 16),
                   "l"(a + (size_t)r * D_ + cg * 8));
        }
        const __half* bsrc = Bg + kt * KT_;
        uint32_t bbase = sb + OFF_B + s * B_STAGE;
        #pragma unroll
        for (int i = 0; i < 4; i++) {              // B: 2048 granules / 512 thr
            int idx = tid + 512 * i;
            int r = idx >> 3, cg = idx & 7;
            asm volatile("cp.async.cg.shared.global [%0], [%1], 16;"
                :: "r"(bbase + r * AS_BYTES + cg * 16),
                   "l"(bsrc + (size_t)r * D_ + cg * 8));
        }
        asm volatile("cp.async.commit_group;");
    };

    issue(0);
    issue(1);
    #pragma unroll 1
    for (int kt = 0; kt < NKT_; kt++) {
        if (kt + 2 < NKT_) {
            issue(kt + 2);
            asm volatile("cp.async.wait_group 2;");
        } else {
            asm volatile("cp.async.wait_group 0;");
        }
        __syncthreads();
        int s = kt % 3;
        uint32_t abase = sb + OFF_A + s * A_STAGE + a_off;
        uint32_t bbase = sb + OFF_B + s * B_STAGE + b_off;
        #pragma unroll
        for (int q = 0; q < 4; q++) {              // 4 x k16 chunks
            uint32_t af[4][4], bf[2][4];
            #pragma unroll
            for (int mi = 0; mi < 4; mi++)
                asm volatile("ldmatrix.sync.aligned.m8n8.x4.shared.b16 {%0,%1,%2,%3}, [%4];"
                    : "=r"(af[mi][0]), "=r"(af[mi][1]), "=r"(af[mi][2]), "=r"(af[mi][3])
                    : "r"(abase + mi * (16 * AS_BYTES) + q * 32));
            #pragma unroll
            for (int p = 0; p < 2; p++)
                asm volatile("ldmatrix.sync.aligned.m8n8.x4.shared.b16 {%0,%1,%2,%3}, [%4];"
                    : "=r"(bf[p][0]), "=r"(bf[p][1]), "=r"(bf[p][2]), "=r"(bf[p][3])
                    : "r"(bbase + p * (16 * AS_BYTES) + q * 32));
            #pragma unroll
            for (int mi = 0; mi < 4; mi++)
                #pragma unroll
                for (int ni = 0; ni < 4; ni++) {
                    const uint32_t* bb = &bf[ni >> 1][(ni & 1) * 2];
                    asm volatile(
                        "mma.sync.aligned.m16n8k16.row.col.f32.f16.f16.f32 "
                        "{%0,%1,%2,%3}, {%4,%5,%6,%7}, {%8,%9}, {%0,%1,%2,%3};"
                        : "+f"(c[mi][ni][0]), "+f"(c[mi][ni][1]),
                          "+f"(c[mi][ni][2]), "+f"(c[mi][ni][3])
                        : "r"(af[mi][0]), "r"(af[mi][1]), "r"(af[mi][2]), "r"(af[mi][3]),
                          "r"(bb[0]), "r"(bb[1]));
                }
        }
        __syncthreads();
    }

    // ---- epilogue: score partial over this CTA's 256 d-cols ----
    float rs0[4] = {0, 0, 0, 0}, rs1[4] = {0, 0, 0, 0};
    #pragma unroll
    for (int mi = 0; mi < 4; mi++) {
        #pragma unroll
        for (int ni = 0; ni < 4; ni++) {
            int d0 = wn * 32 + ni * 8 + 2 * (lane & 3);
            float q0 = sqk[d0], q1 = sqk[d0 + 1];
            float w0 = swv[d0], w1 = swv[d0 + 1];
            rs0[mi] = fmaf(w0, tanh_fast(q0 + c[mi][ni][0]), rs0[mi]);
            rs0[mi] = fmaf(w1, tanh_fast(q1 + c[mi][ni][1]), rs0[mi]);
            rs1[mi] = fmaf(w0, tanh_fast(q0 + c[mi][ni][2]), rs1[mi]);
            rs1[mi] = fmaf(w1, tanh_fast(q1 + c[mi][ni][3]), rs1[mi]);
        }
        rs0[mi] += __shfl_xor_sync(0xffffffffu, rs0[mi], 1);
        rs0[mi] += __shfl_xor_sync(0xffffffffu, rs0[mi], 2);
        rs1[mi] += __shfl_xor_sync(0xffffffffu, rs1[mi], 1);
        rs1[mi] += __shfl_xor_sync(0xffffffffu, rs1[mi], 2);
    }
    float* sp = (float*)(sm + OFF_SP);             // [16 warps][64 rows]
    if ((lane & 3) == 0) {
        int g = lane >> 2;
        #pragma unroll
        for (int mi = 0; mi < 4; mi++) {
            sp[warp * 64 + mi * 16 + g]     = rs0[mi];
            sp[warp * 64 + mi * 16 + g + 8] = rs1[mi];
        }
    }
    __syncthreads();
    if (tid < MT_) {
        int wm2 = tid >> 6, rl = tid & 63;
        float s = 0.0f;
        #pragma unroll
        for (int w = 0; w < 8; w++)
            s += sp[(wm2 * 8 + w) * 64 + rl];
        atomicAdd(&g_scores[arow0 + tid], s);
    }
}

// ================= kernel 3: softmax over Ti=4096 per batch =================
__device__ __forceinline__ float warpMax(float v) {
    #pragma unroll
    for (int o = 16; o; o >>= 1) v = fmaxf(v, __shfl_xor_sync(0xffffffffu, v, o));
    return v;
}
__device__ __forceinline__ float warpSum(float v) {
    #pragma unroll
    for (int o = 16; o; o >>= 1) v += __shfl_xor_sync(0xffffffffu, v, o);
    return v;
}

__global__ void softmax_kernel(float* __restrict__ attn) {
    int b = blockIdx.x, tid = threadIdx.x;         // 256 threads
    __shared__ float red[8];
    __shared__ float bc;
    const float* s = g_scores + b * TI_;
    float v[16];
    float mx = -3.0e38f;
    #pragma unroll
    for (int i = 0; i < 16; i++) { v[i] = s[tid + 256 * i]; mx = fmaxf(mx, v[i]); }
    mx = warpMax(mx);
    if ((tid & 31) == 0) red[tid >> 5] = mx;
    __syncthreads();
    if (tid < 32) { float m = (tid < 8) ? red[tid] : -3.0e38f; m = warpMax(m); if (tid == 0) bc = m; }
    __syncthreads();
    mx = bc;
    float sum = 0.0f;
    #pragma unroll
    for (int i = 0; i < 16; i++) { v[i] = __expf(v[i] - mx); sum += v[i]; }
    sum = warpSum(sum);
    if ((tid & 31) == 0) red[tid >> 5] = sum;
    __syncthreads();
    if (tid < 32) { float m = (tid < 8) ? red[tid] : 0.0f; m = warpSum(m); if (tid == 0) bc = m; }
    __syncthreads();
    float inv = 1.0f / bc;
    #pragma unroll
    for (int i = 0; i < 16; i++) attn[b * TI_ + tid + 256 * i] = v[i] * inv;
}

// ================= kernel 4: mix[b,d] = sum_t attn[b,t]*context[b,t,d] =================
#define MIX_SPLIT 32
#define MIX_TPB   (TI_ / MIX_SPLIT)   // 128 rows per block

__global__ void mix_kernel(const float* __restrict__ attn, const float* __restrict__ ctx,
                           float* __restrict__ mix) {
    int b = blockIdx.y, z = blockIdx.x, d = threadIdx.x;   // 512 threads
    __shared__ float sa[MIX_TPB];
    if (d < MIX_TPB) sa[d] = attn[b * TI_ + z * MIX_TPB + d];
    __syncthreads();
    const float* base = ctx + ((size_t)b * TI_ + (size_t)z * MIX_TPB) * D_ + d;
    float acc = 0.0f;
    #pragma unroll 8
    for (int t = 0; t < MIX_TPB; t++)
        acc = fmaf(sa[t], base[(size_t)t * D_], acc);
    atomicAdd(&mix[b * D_ + d], acc);
}

// ================= kernel 5: out = tanh([mix, output] @ Wo^T + bo) =================
__global__ void out_kernel(const float* __restrict__ mix, const float* __restrict__ out_in,
                           const float* __restrict__ Wo, const float* __restrict__ bo,
                           float* __restrict__ out) {
    int b = blockIdx.x, d = threadIdx.x;           // 512 threads
    __shared__ float comb[2 * D_];
    comb[d] = mix[b * D_ + d];
    comb[D_ + d] = out_in[b * D_ + d];
    __syncthreads();
    const float4* w = (const float4*)(Wo + (size_t)d * (2 * D_));
    float acc = bo[d];
    #pragma unroll 8
    for (int j = 0; j < (2 * D_) / 4; j++) {
        float4 t = w[j];
        acc = fmaf(t.x, comb[4*j], acc);
        acc = fmaf(t.y, comb[4*j+1], acc);
        acc = fmaf(t.z, comb[4*j+2], acc);
        acc = fmaf(t.w, comb[4*j+3], acc);
    }
    out[b * D_ + d] = tanhf(acc);
}

// ================= host launch =================
extern "C" void kernel_launch(void* const* d_in, const int* in_sizes, int n_in,
                              void* d_out, int out_size) {
    (void)in_sizes; (void)n_in; (void)out_size;
    const float* out_in  = (const float*)d_in[0];
    const float* context = (const float*)d_in[1];
    const float* Wq      = (const float*)d_in[2];
    const float* bq      = (const float*)d_in[3];
    const float* Wk      = (const float*)d_in[4];
    const float* bk      = (const float*)d_in[5];
    const float* Wv      = (const float*)d_in[6];
    const float* Wo      = (const float*)d_in[8];
    const float* bo      = (const float*)d_in[9];

    float* o_out  = (float*)d_out;                 // [32,1,512]
    float* o_attn = o_out + B_ * D_;               // [32,1,4096]
    float* o_mix  = o_attn + B_ * TI_;             // [32,1,512]

    static bool attr_done = false;
    if (!attr_done) {
        cudaFuncSetAttribute(scores_kernel, cudaFuncAttributeMaxDynamicSharedMemorySize, SMEM_BYTES);
        attr_done = true;
    }

    cvt_kernel<<<(ROWS_ * D_ + D_ * D_) / 4 / 256, 256>>>(context, Wk);
    qk_kernel<<<B_, D_>>>(out_in, Wq, bq, bk, o_mix);
    // 3 dummies so ncu (-s 5 -c 1) captures scores_kernel as launch #6
    dummy_kernel<<<1, 32>>>();
    dummy_kernel<<<1, 32>>>();
    dummy_kernel<<<1, 32>>>();
    scores_kernel<<<dim3(NTILES_, 2), 512, SMEM_BYTES>>>(Wv);
    softmax_kernel<<<B_, 256>>>(o_attn);
    mix_kernel<<<dim3(MIX_SPLIT, B_), D_>>>(o_attn, context, o_mix);
    out_kernel<<<B_, D_>>>(o_mix, out_in, Wo, bo, o_out);
}